// round 11
// baseline (speedup 1.0000x reference)
#include <cuda_runtime.h>
#include <cstdint>

// Problem constants
#define Tn   1024
#define Bn   64
#define Dn   32
#define Hn   512
#define KK   544            // H + D concatenated K
#define NG   4              // independent batch groups
#define GC   32             // CTAs per group
#define BG   16             // batches per group
#define HB2  (Hn * BG)      // 8192 floats per group-step
#define NCTA 128
#define NTHR 256
#define RPAD 68

// Device-global scratch (zero-initialized at module load)
__device__ float g_xT  [(size_t)Tn * Dn * Bn];               // [t][d][b]
__device__ float g_hist[(size_t)(Tn + 1) * NG * HB2];        // [t][g][h][bl]
__device__ __align__(128) unsigned g_flags[NCTA * 32];       // 1 flag / 128B line

// SMEM layout (floats)
#define SM_W    (KK * 64)        // W slice k-major [k][r]        139264 B
#define SM_HD   (KK * 32)        // (h|x) duplicated [k][(b,b)]    69632 B
#define SM_R    (4 * 16 * RPAD)  // k-seg partials [seg][b][rpad]  17408 B
#define SM_G    (16 * RPAD)      // reduced gates [b][rpad]         4352 B
#define SM_BIAS 64
#define SMEM_FLOATS (SM_W + SM_HD + SM_R + SM_G + SM_BIAS)
#define SMEM_BYTES  (SMEM_FLOATS * 4)

#define L2E 1.4426950408889634f

__device__ __forceinline__ float ex2f(float x) {
    float y; asm("ex2.approx.ftz.f32 %0, %1;" : "=f"(y) : "f"(x)); return y;
}
__device__ __forceinline__ float rcpf(float x) {
    float y; asm("rcp.approx.ftz.f32 %0, %1;" : "=f"(y) : "f"(x)); return y;
}

// One-time waits (preamble/tail): lane-parallel poll with backoff
__device__ __forceinline__ void poll_flag_sleep(const unsigned* fptr,
                                                unsigned tgt) {
    for (;;) {
        unsigned v;
        asm volatile("ld.acquire.gpu.global.u32 %0, [%1];"
                     : "=r"(v) : "l"(fptr) : "memory");
        if (!__any_sync(0xFFFFFFFFu, (int)(v - tgt) < 0)) break;
        __nanosleep(32);
    }
}

__device__ __forceinline__ void publish(unsigned* flag, unsigned val) {
    asm volatile("st.release.gpu.global.u32 [%0], %1;"
                 :: "l"(flag), "r"(val) : "memory");
}

extern __shared__ float smem[];

// ===========================================================================
// ONE fused persistent kernel: transpose + init + LSTM recurrence + conv
// Seg-pipelined: warp-pair s owns k-seg s = h rows [128s,128s+128) U
// x rows [512+8s, 512+8s+8); it polls/stages/computes independently.
// ===========================================================================
__global__ void __launch_bounds__(NTHR, 1) lstm_fused_kernel(
    const float* __restrict__ x,      // (B, D, T)
    const float* __restrict__ W_ih,   // (4H, D)
    const float* __restrict__ W_hh,   // (4H, H)
    const float* __restrict__ b_ih,   // (4H,)
    const float* __restrict__ b_hh,   // (4H,)
    const float* __restrict__ cw,     // (1, H, 1)
    const float* __restrict__ cb,     // (1,)
    float* __restrict__ out)          // (B, 1, T)
{
    float* sm_w    = smem;                     // [544 k][64 r]
    float* sm_hd   = smem + SM_W;              // [544 k][32] (16 b dup)
    float* sm_r    = sm_hd + SM_HD;            // [4 seg][16 b][RPAD]
    float* sm_g    = sm_r + SM_R;              // [16 b][RPAD]
    float* sm_bias = sm_g + SM_G;              // [64]

    const int tid = threadIdx.x;
    const int cta = blockIdx.x;
    const int g   = cta >> 5;                  // group 0..3
    const int c   = cta & 31;                  // cta within group

    // Epoch base (all CTAs end each replay at base + Tn + 1)
    const unsigned base = g_flags[cta * 32];

    // ---- phase A: transpose x (B,D,T) -> g_xT (T,D,B); this CTA's 1/128 ----
    {
        const float4* x4 = (const float4*)x;
        for (int i = tid; i < 4096; i += NTHR) {
            int idx4 = cta * 4096 + i;
            float4 v = __ldcg(x4 + idx4);
            int t0 = (idx4 & 255) * 4;
            int d  = (idx4 >> 8) & 31;
            int b  = idx4 >> 13;
            float* dst = g_xT + d * 64 + b;
            dst[(size_t)(t0 + 0) * 2048] = v.x;
            dst[(size_t)(t0 + 1) * 2048] = v.y;
            dst[(size_t)(t0 + 2) * 2048] = v.z;
            dst[(size_t)(t0 + 3) * 2048] = v.w;
        }
    }
    // zero own h(0) rows
    g_hist[(size_t)g * HB2 + c * 256 + tid] = 0.f;

    // ---- load W slice k-major (+ bias) ----
    for (int r = 0; r < 64; ++r) {
        int n = (r >> 4) * Hn + c * 16 + (r & 15);
        for (int k = tid; k < KK; k += NTHR) {
            float w = (k < Hn) ? W_hh[(size_t)n * Hn + k]
                               : W_ih[(size_t)n * Dn + (k - Hn)];
            sm_w[k * 64 + r] = w;
        }
    }
    if (tid < 64) {
        int n = (tid >> 4) * Hn + c * 16 + (tid & 15);
        sm_bias[tid] = b_ih[n] + b_hh[n];
    }

    __syncthreads();
    if (tid == 0) publish(&g_flags[cta * 32], base + 1);
    // wait for ALL 128 CTAs (transpose is global)
    if (tid < 128) poll_flag_sleep(&g_flags[tid * 32], base + 1);
    __syncthreads();

    // ---- pre-stage h_0 + x_0 (full burst, duplicated) ----
    {
        const float4* src = (const float4*)(g_hist + (size_t)g * HB2);
        #pragma unroll
        for (int i = 0; i < 8; ++i) {
            int idx = tid + i * NTHR;
            float4 v = __ldcg(src + idx);
            int k = idx >> 2, q = idx & 3;
            float4* d0 = (float4*)(sm_hd + k * 32 + q * 8);
            d0[0] = make_float4(v.x, v.x, v.y, v.y);
            d0[1] = make_float4(v.z, v.z, v.w, v.w);
        }
        if (tid < 128) {
            int d = tid >> 2, q = tid & 3;
            const float4* sx = (const float4*)(g_xT + d * 64 + g * 16);
            float4 v = __ldcg(sx + q);
            float4* d0 = (float4*)(sm_hd + (512 + d) * 32 + q * 8);
            d0[0] = make_float4(v.x, v.x, v.y, v.y);
            d0[1] = make_float4(v.z, v.z, v.w, v.w);
        }
    }
    __syncthreads();

    // ---- mappings ----
    const int wrp = tid >> 5, lane = tid & 31;
    const int seg = tid >> 6;                          // k-segment 0..3
    const int tq  = tid & 63;
    const int npp = tq >> 2;                           // r-quad 0..15
    const int bq  = tq & 3;                            // b-quad 0..3
    const int kh0 = seg * 128;                         // h-rows of seg
    const int kx0 = 512 + seg * 8;                     // x-rows of seg
    const ulonglong2* wp = (const ulonglong2*)sm_w;    // + k*16 + npp
    const ulonglong2* hp = (const ulonglong2*)sm_hd;   // + k*8  + bq*2

    // epilogue mapping: 1 cell per thread
    const int bl = tid & 15, hl = tid >> 4;
    float c_reg = 0.f;

    // staging: warp wrp handles chunks j0..j0+3 of its seg
    const int j0 = 8 * (wrp >> 1) + (wrp & 1) * 4;

    for (int t = 0; t < Tn; ++t) {
        // ---- per-pair: poll own sources, stage own seg (t>0) ----
        if (t > 0) {
            const unsigned tgt = base + (unsigned)t + 1;
            {
                const unsigned* fp = &g_flags[(g * 32 + j0 + lane) * 32];
                unsigned v = tgt;
                for (;;) {
                    if (lane < 4)
                        asm volatile("ld.acquire.gpu.global.u32 %0, [%1];"
                                     : "=r"(v) : "l"(fp) : "memory");
                    if (__all_sync(0xFFFFFFFFu, (int)(v - tgt) >= 0)) break;
                }
            }
            const float4* hsrc = (const float4*)
                (g_hist + ((size_t)t * NG + g) * HB2);
            #pragma unroll
            for (int jj = 0; jj < 4; ++jj) {
                int j = j0 + jj;
                if (j == c) continue;       // own chunk self-staged
                #pragma unroll
                for (int m = 0; m < 2; ++m) {
                    int f = lane + m * 32;               // 0..63
                    float4 hv = __ldcg(hsrc + j * 64 + f);
                    int kl = f >> 2, q = f & 3;
                    float4* d0 = (float4*)(sm_hd + (j * 16 + kl) * 32 + q * 8);
                    d0[0] = make_float4(hv.x, hv.x, hv.y, hv.y);
                    d0[1] = make_float4(hv.z, hv.z, hv.w, hv.w);
                }
            }
            if (wrp & 1) {                  // odd warp of pair: x-slice
                int d = seg * 8 + (lane >> 2), q = lane & 3;
                const float4* sx = (const float4*)
                    (g_xT + (size_t)t * 2048 + d * 64 + g * 16);
                float4 v = __ldcg(sx + q);
                float4* d0 = (float4*)(sm_hd + (512 + d) * 32 + q * 8);
                d0[0] = make_float4(v.x, v.x, v.y, v.y);
                d0[1] = make_float4(v.z, v.z, v.w, v.w);
            }
        }
        // pair-local barrier: seg fully staged
        asm volatile("bar.sync %0, 64;" :: "r"(1 + seg) : "memory");

        // ---- GEMM seg: 128 h-rows + 8 x-rows; acc (4r x 4b) as 8 f32x2 ----
        unsigned long long a0 = 0, a1 = 0, a2 = 0, a3 = 0;
        unsigned long long a4 = 0, a5 = 0, a6 = 0, a7 = 0;
        #pragma unroll 8
        for (int kk = 0; kk < 128; ++kk) {
            int k = kh0 + kk;
            ulonglong2 w2 = wp[k * 16 + npp];
            ulonglong2 h0 = hp[k * 8 + bq * 2];
            ulonglong2 h1 = hp[k * 8 + bq * 2 + 1];
            asm("fma.rn.f32x2 %0, %1, %2, %0;" : "+l"(a0) : "l"(w2.x), "l"(h0.x));
            asm("fma.rn.f32x2 %0, %1, %2, %0;" : "+l"(a1) : "l"(w2.x), "l"(h0.y));
            asm("fma.rn.f32x2 %0, %1, %2, %0;" : "+l"(a2) : "l"(w2.x), "l"(h1.x));
            asm("fma.rn.f32x2 %0, %1, %2, %0;" : "+l"(a3) : "l"(w2.x), "l"(h1.y));
            asm("fma.rn.f32x2 %0, %1, %2, %0;" : "+l"(a4) : "l"(w2.y), "l"(h0.x));
            asm("fma.rn.f32x2 %0, %1, %2, %0;" : "+l"(a5) : "l"(w2.y), "l"(h0.y));
            asm("fma.rn.f32x2 %0, %1, %2, %0;" : "+l"(a6) : "l"(w2.y), "l"(h1.x));
            asm("fma.rn.f32x2 %0, %1, %2, %0;" : "+l"(a7) : "l"(w2.y), "l"(h1.y));
        }
        #pragma unroll
        for (int kk = 0; kk < 8; ++kk) {
            int k = kx0 + kk;
            ulonglong2 w2 = wp[k * 16 + npp];
            ulonglong2 h0 = hp[k * 8 + bq * 2];
            ulonglong2 h1 = hp[k * 8 + bq * 2 + 1];
            asm("fma.rn.f32x2 %0, %1, %2, %0;" : "+l"(a0) : "l"(w2.x), "l"(h0.x));
            asm("fma.rn.f32x2 %0, %1, %2, %0;" : "+l"(a1) : "l"(w2.x), "l"(h0.y));
            asm("fma.rn.f32x2 %0, %1, %2, %0;" : "+l"(a2) : "l"(w2.x), "l"(h1.x));
            asm("fma.rn.f32x2 %0, %1, %2, %0;" : "+l"(a3) : "l"(w2.x), "l"(h1.y));
            asm("fma.rn.f32x2 %0, %1, %2, %0;" : "+l"(a4) : "l"(w2.y), "l"(h0.x));
            asm("fma.rn.f32x2 %0, %1, %2, %0;" : "+l"(a5) : "l"(w2.y), "l"(h0.y));
            asm("fma.rn.f32x2 %0, %1, %2, %0;" : "+l"(a6) : "l"(w2.y), "l"(h1.x));
            asm("fma.rn.f32x2 %0, %1, %2, %0;" : "+l"(a7) : "l"(w2.y), "l"(h1.y));
        }

        // ---- store partials [seg][b][r] ----
        {
            float2 p0 = *(float2*)&a0, p4 = *(float2*)&a4;
            float2 p1 = *(float2*)&a1, p5 = *(float2*)&a5;
            float2 p2 = *(float2*)&a2, p6 = *(float2*)&a6;
            float2 p3 = *(float2*)&a3, p7 = *(float2*)&a7;
            float* bp = sm_r + (seg * 16 + bq * 4) * RPAD + npp * 4;
            *(float4*)(bp + 0 * RPAD) = make_float4(p0.x, p0.y, p4.x, p4.y);
            *(float4*)(bp + 1 * RPAD) = make_float4(p1.x, p1.y, p5.x, p5.y);
            *(float4*)(bp + 2 * RPAD) = make_float4(p2.x, p2.y, p6.x, p6.y);
            *(float4*)(bp + 3 * RPAD) = make_float4(p3.x, p3.y, p7.x, p7.y);
        }
        __syncthreads();

        // ---- reduce 4 segments -> sm_g[b][r] ----
        {
            int b = tid >> 4, nq = tid & 15;
            const float* rb = sm_r + b * RPAD + nq * 4;
            float4 s0 = *(const float4*)(rb);
            float4 s1 = *(const float4*)(rb + 16 * RPAD);
            float4 s2 = *(const float4*)(rb + 32 * RPAD);
            float4 s3 = *(const float4*)(rb + 48 * RPAD);
            *(float4*)(sm_g + b * RPAD + nq * 4) =
                make_float4(s0.x + s1.x + s2.x + s3.x,
                            s0.y + s1.y + s2.y + s3.y,
                            s0.z + s1.z + s2.z + s3.z,
                            s0.w + s1.w + s2.w + s3.w);
        }
        __syncthreads();

        // ---- LSTM cell epilogue (division-free, 5 EX2 + 3 RCP) ----
        {
            float xi = sm_g[bl * RPAD +  0 + hl] + sm_bias[ 0 + hl];
            float xf = sm_g[bl * RPAD + 16 + hl] + sm_bias[16 + hl];
            float xg = sm_g[bl * RPAD + 32 + hl] + sm_bias[32 + hl];
            float xo = sm_g[bl * RPAD + 48 + hl] + sm_bias[48 + hl];
            float ei = ex2f(-xi * L2E);
            float ef = ex2f(-xf * L2E);
            float eo = ex2f(-xo * L2E);
            float eg = ex2f(-2.f * xg * L2E);
            float di = 1.f + ei, df = 1.f + ef, dc = 1.f + eo, dg = 1.f + eg;
            float r0 = rcpf(di * df);
            float ii = r0 * df, ff = r0 * di;
            float r1 = rcpf(dc * dg);
            float oo = r1 * dg;
            float tg = (1.f - eg) * (r1 * dc);
            c_reg = ff * c_reg + ii * tg;
            float ec = ex2f(-2.f * c_reg * L2E);
            float tc = (1.f - ec) * rcpf(1.f + ec);
            float h  = oo * tc;
            g_hist[((size_t)(t + 1) * NG + g) * HB2 + c * 256 + tid] = h;
            // self-stage own rows (for step t+1) straight from registers
            *(float2*)(sm_hd + (c * 16 + hl) * 32 + bl * 2) = make_float2(h, h);
        }
        __syncthreads();
        if (tid == 0) publish(&g_flags[cta * 32], base + (unsigned)t + 2);
    }

    // ================= conv tail =================
    if (tid < 32)
        poll_flag_sleep(&g_flags[(g * 32 + tid) * 32], base + Tn + 1);
    __syncthreads();

    float* scw  = sm_w;      // reuse
    float* sred = sm_r;
    for (int i = tid; i < Hn; i += NTHR) scw[i] = cw[i];
    const float cbv = cb[0];
    __syncthreads();

    const int cbl = tid & 15, hq = tid >> 4;     // 16 h-chunks of 32
    for (int j = 0; j < Tn / GC; ++j) {
        int t = c * (Tn / GC) + j;
        const float* hp2 = g_hist + ((size_t)(t + 1) * NG + g) * HB2 + cbl;
        float acc = 0.f;
        #pragma unroll 8
        for (int h = hq * 32; h < hq * 32 + 32; ++h)
            acc += __ldcg(hp2 + (size_t)h * BG) * scw[h];
        sred[tid] = acc;
        __syncthreads();
        if (tid < 16) {
            float s = cbv;
            #pragma unroll
            for (int q = 0; q < 16; ++q) s += sred[q * 16 + tid];
            out[(size_t)(g * 16 + tid) * Tn + t] = s;
        }
        __syncthreads();
    }
}

// ---------------------------------------------------------------------------
extern "C" void kernel_launch(void* const* d_in, const int* in_sizes, int n_in,
                              void* d_out, int out_size)
{
    const float* x    = (const float*)d_in[0];
    const float* W_ih = (const float*)d_in[1];
    const float* W_hh = (const float*)d_in[2];
    const float* b_ih = (const float*)d_in[3];
    const float* b_hh = (const float*)d_in[4];
    const float* cw   = (const float*)d_in[5];
    const float* cb   = (const float*)d_in[6];
    float* out = (float*)d_out;

    cudaFuncSetAttribute(lstm_fused_kernel,
                         cudaFuncAttributeMaxDynamicSharedMemorySize, SMEM_BYTES);
    lstm_fused_kernel<<<NCTA, NTHR, SMEM_BYTES>>>(x, W_ih, W_hh, b_ih, b_hh,
                                                  cw, cb, out);
}

// round 12
// speedup vs baseline: 1.0006x; 1.0006x over previous
#include <cuda_runtime.h>
#include <cstdint>

// Problem constants
#define Tn   1024
#define Bn   64
#define Dn   32
#define Hn   512
#define KK   544            // H + D concatenated K
#define NG   4              // independent batch groups
#define GC   32             // CTAs per group
#define BG   16             // batches per group
#define HB2  (Hn * BG)      // 8192 floats per group-step
#define NCTA 128
#define NTHR 256
#define RPAD 68

// Device-global scratch (zero-initialized at module load)
__device__ float g_xT  [(size_t)Tn * Dn * Bn];               // [t][d][b]
__device__ float g_hist[(size_t)(Tn + 1) * NG * HB2];        // [t][g][h][bl]
__device__ __align__(128) unsigned g_flags[NCTA * 32];       // 1 flag / 128B line

// SMEM layout (floats)
#define SM_W    (KK * 64)        // W slice k-major [k][r]        139264 B
#define SM_HD   (KK * 32)        // (h|x) duplicated [k][(b,b)]    69632 B
#define SM_R    (4 * 16 * RPAD)  // k-seg partials [seg][b][rpad]  17408 B
#define SM_G    (16 * RPAD)      // reduced gates [b][rpad]         4352 B
#define SM_BIAS 64
#define SMEM_FLOATS (SM_W + SM_HD + SM_R + SM_G + SM_BIAS)
#define SMEM_BYTES  (SMEM_FLOATS * 4)

#define L2E 1.4426950408889634f

__device__ __forceinline__ float ex2f(float x) {
    float y; asm("ex2.approx.ftz.f32 %0, %1;" : "=f"(y) : "f"(x)); return y;
}
__device__ __forceinline__ float rcpf(float x) {
    float y; asm("rcp.approx.ftz.f32 %0, %1;" : "=f"(y) : "f"(x)); return y;
}

// One-time waits (preamble/tail): lane-parallel poll with backoff
__device__ __forceinline__ void poll_flag_sleep(const unsigned* fptr,
                                                unsigned tgt) {
    for (;;) {
        unsigned v;
        asm volatile("ld.acquire.gpu.global.u32 %0, [%1];"
                     : "=r"(v) : "l"(fptr) : "memory");
        if (!__any_sync(0xFFFFFFFFu, (int)(v - tgt) < 0)) break;
        __nanosleep(32);
    }
}

__device__ __forceinline__ void publish(unsigned* flag, unsigned val) {
    asm volatile("st.release.gpu.global.u32 [%0], %1;"
                 :: "l"(flag), "r"(val) : "memory");
}

extern __shared__ float smem[];

// ===========================================================================
// ONE fused persistent kernel: transpose + init + LSTM recurrence + conv
// Seg-pipelined: warp-pair s owns k-seg s = h rows [128s,128s+128) U
// x rows [512+8s, 512+8s+8); it polls/stages/computes independently.
// ===========================================================================
__global__ void __launch_bounds__(NTHR, 1) lstm_fused_kernel(
    const float* __restrict__ x,      // (B, D, T)
    const float* __restrict__ W_ih,   // (4H, D)
    const float* __restrict__ W_hh,   // (4H, H)
    const float* __restrict__ b_ih,   // (4H,)
    const float* __restrict__ b_hh,   // (4H,)
    const float* __restrict__ cw,     // (1, H, 1)
    const float* __restrict__ cb,     // (1,)
    float* __restrict__ out)          // (B, 1, T)
{
    float* sm_w    = smem;                     // [544 k][64 r]
    float* sm_hd   = smem + SM_W;              // [544 k][32] (16 b dup)
    float* sm_r    = sm_hd + SM_HD;            // [4 seg][16 b][RPAD]
    float* sm_g    = sm_r + SM_R;              // [16 b][RPAD]
    float* sm_bias = sm_g + SM_G;              // [64]

    const int tid = threadIdx.x;
    const int cta = blockIdx.x;
    const int g   = cta >> 5;                  // group 0..3
    const int c   = cta & 31;                  // cta within group

    // Epoch base (all CTAs end each replay at base + Tn + 1)
    const unsigned base = g_flags[cta * 32];

    // ---- phase A: transpose x (B,D,T) -> g_xT (T,D,B); this CTA's 1/128 ----
    {
        const float4* x4 = (const float4*)x;
        for (int i = tid; i < 4096; i += NTHR) {
            int idx4 = cta * 4096 + i;
            float4 v = __ldcg(x4 + idx4);
            int t0 = (idx4 & 255) * 4;
            int d  = (idx4 >> 8) & 31;
            int b  = idx4 >> 13;
            float* dst = g_xT + d * 64 + b;
            dst[(size_t)(t0 + 0) * 2048] = v.x;
            dst[(size_t)(t0 + 1) * 2048] = v.y;
            dst[(size_t)(t0 + 2) * 2048] = v.z;
            dst[(size_t)(t0 + 3) * 2048] = v.w;
        }
    }
    // zero own h(0) rows
    g_hist[(size_t)g * HB2 + c * 256 + tid] = 0.f;

    // ---- load W slice k-major (+ bias) ----
    for (int r = 0; r < 64; ++r) {
        int n = (r >> 4) * Hn + c * 16 + (r & 15);
        for (int k = tid; k < KK; k += NTHR) {
            float w = (k < Hn) ? W_hh[(size_t)n * Hn + k]
                               : W_ih[(size_t)n * Dn + (k - Hn)];
            sm_w[k * 64 + r] = w;
        }
    }
    if (tid < 64) {
        int n = (tid >> 4) * Hn + c * 16 + (tid & 15);
        sm_bias[tid] = b_ih[n] + b_hh[n];
    }

    __syncthreads();
    if (tid == 0) publish(&g_flags[cta * 32], base + 1);
    // wait for ALL 128 CTAs (transpose is global)
    if (tid < 128) poll_flag_sleep(&g_flags[tid * 32], base + 1);
    __syncthreads();

    // ---- pre-stage h_0 + x_0 (full burst, duplicated) ----
    {
        const float4* src = (const float4*)(g_hist + (size_t)g * HB2);
        #pragma unroll
        for (int i = 0; i < 8; ++i) {
            int idx = tid + i * NTHR;
            float4 v = __ldcg(src + idx);
            int k = idx >> 2, q = idx & 3;
            float4* d0 = (float4*)(sm_hd + k * 32 + q * 8);
            d0[0] = make_float4(v.x, v.x, v.y, v.y);
            d0[1] = make_float4(v.z, v.z, v.w, v.w);
        }
        if (tid < 128) {
            int d = tid >> 2, q = tid & 3;
            const float4* sx = (const float4*)(g_xT + d * 64 + g * 16);
            float4 v = __ldcg(sx + q);
            float4* d0 = (float4*)(sm_hd + (512 + d) * 32 + q * 8);
            d0[0] = make_float4(v.x, v.x, v.y, v.y);
            d0[1] = make_float4(v.z, v.z, v.w, v.w);
        }
    }
    __syncthreads();

    // ---- mappings ----
    const int wrp = tid >> 5, lane = tid & 31;
    const int seg = tid >> 6;                          // k-segment 0..3
    const int tq  = tid & 63;
    const int npp = tq >> 2;                           // r-quad 0..15
    const int bq  = tq & 3;                            // b-quad 0..3
    const int kh0 = seg * 128;                         // h-rows of seg
    const int kx0 = 512 + seg * 8;                     // x-rows of seg
    const ulonglong2* wp = (const ulonglong2*)sm_w;    // + k*16 + npp
    const ulonglong2* hp = (const ulonglong2*)sm_hd;   // + k*8  + bq*2

    // epilogue mapping: 1 cell per thread
    const int bl = tid & 15, hl = tid >> 4;
    float c_reg = 0.f;

    // staging: warp wrp handles chunks j0..j0+3 of its seg
    const int j0 = 8 * (wrp >> 1) + (wrp & 1) * 4;

    for (int t = 0; t < Tn; ++t) {
        // ---- per-pair: poll own sources, stage own seg (t>0) ----
        if (t > 0) {
            const unsigned tgt = base + (unsigned)t + 1;
            {
                const unsigned* fp = &g_flags[(g * 32 + j0 + lane) * 32];
                unsigned v = tgt;
                for (;;) {
                    if (lane < 4)
                        asm volatile("ld.acquire.gpu.global.u32 %0, [%1];"
                                     : "=r"(v) : "l"(fp) : "memory");
                    if (__all_sync(0xFFFFFFFFu, (int)(v - tgt) >= 0)) break;
                }
            }
            const float4* hsrc = (const float4*)
                (g_hist + ((size_t)t * NG + g) * HB2);
            #pragma unroll
            for (int jj = 0; jj < 4; ++jj) {
                int j = j0 + jj;
                if (j == c) continue;       // own chunk self-staged
                #pragma unroll
                for (int m = 0; m < 2; ++m) {
                    int f = lane + m * 32;               // 0..63
                    float4 hv = __ldcg(hsrc + j * 64 + f);
                    int kl = f >> 2, q = f & 3;
                    float4* d0 = (float4*)(sm_hd + (j * 16 + kl) * 32 + q * 8);
                    d0[0] = make_float4(hv.x, hv.x, hv.y, hv.y);
                    d0[1] = make_float4(hv.z, hv.z, hv.w, hv.w);
                }
            }
            if (wrp & 1) {                  // odd warp of pair: x-slice
                int d = seg * 8 + (lane >> 2), q = lane & 3;
                const float4* sx = (const float4*)
                    (g_xT + (size_t)t * 2048 + d * 64 + g * 16);
                float4 v = __ldcg(sx + q);
                float4* d0 = (float4*)(sm_hd + (512 + d) * 32 + q * 8);
                d0[0] = make_float4(v.x, v.x, v.y, v.y);
                d0[1] = make_float4(v.z, v.z, v.w, v.w);
            }
        }
        // pair-local barrier: seg fully staged
        asm volatile("bar.sync %0, 64;" :: "r"(1 + seg) : "memory");

        // ---- GEMM seg: 128 h-rows + 8 x-rows; acc (4r x 4b) as 8 f32x2 ----
        unsigned long long a0 = 0, a1 = 0, a2 = 0, a3 = 0;
        unsigned long long a4 = 0, a5 = 0, a6 = 0, a7 = 0;
        #pragma unroll 8
        for (int kk = 0; kk < 128; ++kk) {
            int k = kh0 + kk;
            ulonglong2 w2 = wp[k * 16 + npp];
            ulonglong2 h0 = hp[k * 8 + bq * 2];
            ulonglong2 h1 = hp[k * 8 + bq * 2 + 1];
            asm("fma.rn.f32x2 %0, %1, %2, %0;" : "+l"(a0) : "l"(w2.x), "l"(h0.x));
            asm("fma.rn.f32x2 %0, %1, %2, %0;" : "+l"(a1) : "l"(w2.x), "l"(h0.y));
            asm("fma.rn.f32x2 %0, %1, %2, %0;" : "+l"(a2) : "l"(w2.x), "l"(h1.x));
            asm("fma.rn.f32x2 %0, %1, %2, %0;" : "+l"(a3) : "l"(w2.x), "l"(h1.y));
            asm("fma.rn.f32x2 %0, %1, %2, %0;" : "+l"(a4) : "l"(w2.y), "l"(h0.x));
            asm("fma.rn.f32x2 %0, %1, %2, %0;" : "+l"(a5) : "l"(w2.y), "l"(h0.y));
            asm("fma.rn.f32x2 %0, %1, %2, %0;" : "+l"(a6) : "l"(w2.y), "l"(h1.x));
            asm("fma.rn.f32x2 %0, %1, %2, %0;" : "+l"(a7) : "l"(w2.y), "l"(h1.y));
        }
        #pragma unroll
        for (int kk = 0; kk < 8; ++kk) {
            int k = kx0 + kk;
            ulonglong2 w2 = wp[k * 16 + npp];
            ulonglong2 h0 = hp[k * 8 + bq * 2];
            ulonglong2 h1 = hp[k * 8 + bq * 2 + 1];
            asm("fma.rn.f32x2 %0, %1, %2, %0;" : "+l"(a0) : "l"(w2.x), "l"(h0.x));
            asm("fma.rn.f32x2 %0, %1, %2, %0;" : "+l"(a1) : "l"(w2.x), "l"(h0.y));
            asm("fma.rn.f32x2 %0, %1, %2, %0;" : "+l"(a2) : "l"(w2.x), "l"(h1.x));
            asm("fma.rn.f32x2 %0, %1, %2, %0;" : "+l"(a3) : "l"(w2.x), "l"(h1.y));
            asm("fma.rn.f32x2 %0, %1, %2, %0;" : "+l"(a4) : "l"(w2.y), "l"(h0.x));
            asm("fma.rn.f32x2 %0, %1, %2, %0;" : "+l"(a5) : "l"(w2.y), "l"(h0.y));
            asm("fma.rn.f32x2 %0, %1, %2, %0;" : "+l"(a6) : "l"(w2.y), "l"(h1.x));
            asm("fma.rn.f32x2 %0, %1, %2, %0;" : "+l"(a7) : "l"(w2.y), "l"(h1.y));
        }

        // ---- store partials [seg][b][r] ----
        {
            float2 p0 = *(float2*)&a0, p4 = *(float2*)&a4;
            float2 p1 = *(float2*)&a1, p5 = *(float2*)&a5;
            float2 p2 = *(float2*)&a2, p6 = *(float2*)&a6;
            float2 p3 = *(float2*)&a3, p7 = *(float2*)&a7;
            float* bp = sm_r + (seg * 16 + bq * 4) * RPAD + npp * 4;
            *(float4*)(bp + 0 * RPAD) = make_float4(p0.x, p0.y, p4.x, p4.y);
            *(float4*)(bp + 1 * RPAD) = make_float4(p1.x, p1.y, p5.x, p5.y);
            *(float4*)(bp + 2 * RPAD) = make_float4(p2.x, p2.y, p6.x, p6.y);
            *(float4*)(bp + 3 * RPAD) = make_float4(p3.x, p3.y, p7.x, p7.y);
        }
        __syncthreads();

        // ---- reduce 4 segments -> sm_g[b][r] ----
        {
            int b = tid >> 4, nq = tid & 15;
            const float* rb = sm_r + b * RPAD + nq * 4;
            float4 s0 = *(const float4*)(rb);
            float4 s1 = *(const float4*)(rb + 16 * RPAD);
            float4 s2 = *(const float4*)(rb + 32 * RPAD);
            float4 s3 = *(const float4*)(rb + 48 * RPAD);
            *(float4*)(sm_g + b * RPAD + nq * 4) =
                make_float4(s0.x + s1.x + s2.x + s3.x,
                            s0.y + s1.y + s2.y + s3.y,
                            s0.z + s1.z + s2.z + s3.z,
                            s0.w + s1.w + s2.w + s3.w);
        }
        __syncthreads();

        // ---- LSTM cell epilogue (division-free, 5 EX2 + 3 RCP) ----
        {
            float xi = sm_g[bl * RPAD +  0 + hl] + sm_bias[ 0 + hl];
            float xf = sm_g[bl * RPAD + 16 + hl] + sm_bias[16 + hl];
            float xg = sm_g[bl * RPAD + 32 + hl] + sm_bias[32 + hl];
            float xo = sm_g[bl * RPAD + 48 + hl] + sm_bias[48 + hl];
            float ei = ex2f(-xi * L2E);
            float ef = ex2f(-xf * L2E);
            float eo = ex2f(-xo * L2E);
            float eg = ex2f(-2.f * xg * L2E);
            float di = 1.f + ei, df = 1.f + ef, dc = 1.f + eo, dg = 1.f + eg;
            float r0 = rcpf(di * df);
            float ii = r0 * df, ff = r0 * di;
            float r1 = rcpf(dc * dg);
            float oo = r1 * dg;
            float tg = (1.f - eg) * (r1 * dc);
            c_reg = ff * c_reg + ii * tg;
            float ec = ex2f(-2.f * c_reg * L2E);
            float tc = (1.f - ec) * rcpf(1.f + ec);
            float h  = oo * tc;
            g_hist[((size_t)(t + 1) * NG + g) * HB2 + c * 256 + tid] = h;
            // self-stage own rows (for step t+1) straight from registers
            *(float2*)(sm_hd + (c * 16 + hl) * 32 + bl * 2) = make_float2(h, h);
        }
        __syncthreads();
        if (tid == 0) publish(&g_flags[cta * 32], base + (unsigned)t + 2);
    }

    // ================= conv tail =================
    if (tid < 32)
        poll_flag_sleep(&g_flags[(g * 32 + tid) * 32], base + Tn + 1);
    __syncthreads();

    float* scw  = sm_w;      // reuse
    float* sred = sm_r;
    for (int i = tid; i < Hn; i += NTHR) scw[i] = cw[i];
    const float cbv = cb[0];
    __syncthreads();

    const int cbl = tid & 15, hq = tid >> 4;     // 16 h-chunks of 32
    for (int j = 0; j < Tn / GC; ++j) {
        int t = c * (Tn / GC) + j;
        const float* hp2 = g_hist + ((size_t)(t + 1) * NG + g) * HB2 + cbl;
        float acc = 0.f;
        #pragma unroll 8
        for (int h = hq * 32; h < hq * 32 + 32; ++h)
            acc += __ldcg(hp2 + (size_t)h * BG) * scw[h];
        sred[tid] = acc;
        __syncthreads();
        if (tid < 16) {
            float s = cbv;
            #pragma unroll
            for (int q = 0; q < 16; ++q) s += sred[q * 16 + tid];
            out[(size_t)(g * 16 + tid) * Tn + t] = s;
        }
        __syncthreads();
    }
}

// ---------------------------------------------------------------------------
extern "C" void kernel_launch(void* const* d_in, const int* in_sizes, int n_in,
                              void* d_out, int out_size)
{
    const float* x    = (const float*)d_in[0];
    const float* W_ih = (const float*)d_in[1];
    const float* W_hh = (const float*)d_in[2];
    const float* b_ih = (const float*)d_in[3];
    const float* b_hh = (const float*)d_in[4];
    const float* cw   = (const float*)d_in[5];
    const float* cb   = (const float*)d_in[6];
    float* out = (float*)d_out;

    cudaFuncSetAttribute(lstm_fused_kernel,
                         cudaFuncAttributeMaxDynamicSharedMemorySize, SMEM_BYTES);
    lstm_fused_kernel<<<NCTA, NTHR, SMEM_BYTES>>>(x, W_ih, W_hh, b_ih, b_hh,
                                                  cw, cb, out);
}

// round 14
// speedup vs baseline: 1.5459x; 1.5450x over previous
#include <cuda_runtime.h>
#include <cuda_bf16.h>
#include <cstdint>

// Problem constants
#define Tn   1024
#define Bn   64
#define Dn   32
#define Hn   512
#define NG   4              // independent batch groups
#define GC   32             // CTAs per group
#define NCTA 128
#define NTHR 256

// Device-global scratch
// h history, packed u32: low16 = bf16(hi), high16 = bf16(lo)
__device__ unsigned g_hpk[(size_t)(Tn + 1) * NG * 16 * 512];  // [t][g][b][k]
__device__ unsigned g_xpk[(size_t)Tn * NG * 16 * 32];         // [t][g][b][d]
__device__ __align__(128) unsigned g_flags[NCTA * 32];        // 1 flag / 128B line

// SMEM layout (bytes)
#define OFF_BIAS  0                     // 64 floats
#define OFF_BHI   256
#define TILE_B    17408                 // 34 ksteps x 2 nt x 64 words x 4B
#define OFF_BLO   (OFF_BHI + TILE_B)    // 17664
#define OFF_R     (OFF_BLO + TILE_B)    // 35072: 4 parts x 64 r x 20 floats
#define SMEM_TOTAL (OFF_R + 4 * 64 * 20 * 4)   // 55552

#define L2E 1.4426950408889634f

__device__ __forceinline__ float ex2f(float x) {
    float y; asm("ex2.approx.ftz.f32 %0, %1;" : "=f"(y) : "f"(x)); return y;
}
__device__ __forceinline__ float rcpf(float x) {
    float y; asm("rcp.approx.ftz.f32 %0, %1;" : "=f"(y) : "f"(x)); return y;
}
// pack fp32 -> {bf16 hi | bf16 lo << 16}
__device__ __forceinline__ unsigned packhl(float v) {
    unsigned hb = (unsigned)__bfloat16_as_ushort(__float2bfloat16(v));
    float hf = __uint_as_float(hb << 16);
    unsigned lb = (unsigned)__bfloat16_as_ushort(__float2bfloat16(v - hf));
    return hb | (lb << 16);
}
__device__ __forceinline__ void sts64(uint32_t a, uint32_t x, uint32_t y) {
    asm volatile("st.shared.v2.b32 [%0], {%1,%2};" :: "r"(a), "r"(x), "r"(y));
}
__device__ __forceinline__ void lds64(uint32_t& x, uint32_t& y, uint32_t a) {
    asm volatile("ld.shared.v2.b32 {%0,%1}, [%2];" : "=r"(x), "=r"(y) : "r"(a));
}
__device__ __forceinline__ void poll_flag_sleep(const unsigned* fptr,
                                                unsigned tgt) {
    for (;;) {
        unsigned v;
        asm volatile("ld.acquire.gpu.global.u32 %0, [%1];"
                     : "=r"(v) : "l"(fptr) : "memory");
        if (!__any_sync(0xFFFFFFFFu, (int)(v - tgt) < 0)) break;
        __nanosleep(32);
    }
}
__device__ __forceinline__ void spin1(const unsigned* fptr, unsigned tgt) {
    unsigned v;
    do {
        asm volatile("ld.acquire.gpu.global.u32 %0, [%1];"
                     : "=r"(v) : "l"(fptr) : "memory");
    } while ((int)(v - tgt) < 0);
}
__device__ __forceinline__ void publish(unsigned* flag, unsigned val) {
    asm volatile("st.release.gpu.global.u32 [%0], %1;"
                 :: "l"(flag), "r"(val) : "memory");
}
// m16n8k16 bf16 mma, fp32 acc (HMMA, valid on base sm_103 target)
#define MMA16816(C, A, B0, B1)                                               \
    asm volatile(                                                            \
        "mma.sync.aligned.m16n8k16.row.col.f32.bf16.bf16.f32 "               \
        "{%0,%1,%2,%3}, {%4,%5,%6,%7}, {%8,%9}, {%0,%1,%2,%3};"              \
        : "+f"((C)[0]), "+f"((C)[1]), "+f"((C)[2]), "+f"((C)[3])             \
        : "r"((A)[0]), "r"((A)[1]), "r"((A)[2]), "r"((A)[3]),                \
          "r"(B0), "r"(B1))

// fetch bf16 bits of W'(row, col): row<64 -> hi(W[row]), row>=64 -> lo(W[row-64])
__device__ __forceinline__ unsigned wbits(const float* __restrict__ Whh,
                                          const float* __restrict__ Wih,
                                          int c, int row, int col) {
    int r = row & 63;
    int n = (r >> 4) * Hn + c * 16 + (r & 15);
    float w = (col < 512) ? Whh[(size_t)n * Hn + col]
                          : Wih[n * Dn + (col - 512)];
    unsigned hb = (unsigned)__bfloat16_as_ushort(__float2bfloat16(w));
    if (row < 64) return hb;
    float hf = __uint_as_float(hb << 16);
    return (unsigned)__bfloat16_as_ushort(__float2bfloat16(w - hf));
}

extern __shared__ char smem[];

// ===========================================================================
__global__ void __launch_bounds__(NTHR, 1) lstm_hmma_kernel(
    const float* __restrict__ x,      // (B, D, T)
    const float* __restrict__ W_ih,   // (4H, D)
    const float* __restrict__ W_hh,   // (4H, H)
    const float* __restrict__ b_ih,   // (4H,)
    const float* __restrict__ b_hh,   // (4H,)
    const float* __restrict__ cw,     // (1, H, 1)
    const float* __restrict__ cb,     // (1,)
    float* __restrict__ out)          // (B, 1, T)
{
    const int tid  = threadIdx.x;
    const int cta  = blockIdx.x;
    const int g    = cta >> 5;
    const int c    = cta & 31;
    const int wid  = tid >> 5, lane = tid & 31;
    const int ms   = wid & 3;          // M-slice (rows 32ms..32ms+31)
    const int kh   = wid >> 2;         // K-half (272 each)
    const int fg   = lane >> 2;        // fragment group id
    const int ft   = lane & 3;         // fragment thread-in-group
    const uint32_t sb = (uint32_t)__cvta_generic_to_shared(smem);
    float* smf     = (float*)smem;
    float* sm_bias = smf + OFF_BIAS / 4;

    const unsigned base = g_flags[cta * 32];

    // ---- preamble: pack x (B,D,T) -> g_xpk[t][g][b][d]; this CTA's 1/128 ----
    {
        const float4* x4 = (const float4*)x;
        for (int i = tid; i < 4096; i += NTHR) {
            int idx4 = cta * 4096 + i;
            float4 v = __ldcg(x4 + idx4);
            int t0 = (idx4 & 255) * 4;
            int d  = (idx4 >> 8) & 31;
            int b  = idx4 >> 13;
            unsigned* dst = g_xpk + ((b >> 4) * 16 + (b & 15)) * 32 + d;
            dst[(size_t)(t0 + 0) * 2048] = packhl(v.x);
            dst[(size_t)(t0 + 1) * 2048] = packhl(v.y);
            dst[(size_t)(t0 + 2) * 2048] = packhl(v.z);
            dst[(size_t)(t0 + 3) * 2048] = packhl(v.w);
        }
    }
    // zero own h(0)
    g_hpk[((size_t)g * 16 + (tid >> 4)) * 512 + c * 16 + (tid & 15)] = 0u;
    if (tid < 64) {
        int n = (tid >> 4) * Hn + c * 16 + (tid & 15);
        sm_bias[tid] = b_ih[n] + b_hh[n];
    }

    // ---- A fragments into registers: a[mt][ks][rg] ----
    unsigned a[2][17][4];
    #pragma unroll
    for (int mt = 0; mt < 2; ++mt) {
        #pragma unroll
        for (int ks = 0; ks < 17; ++ks) {
            #pragma unroll
            for (int rg = 0; rg < 4; ++rg) {
                int row = 32 * ms + 16 * mt + fg + (rg & 1) * 8;
                int col = 272 * kh + 16 * ks + 2 * ft + (rg >> 1) * 8;
                unsigned w0 = wbits(W_hh, W_ih, c, row, col);
                unsigned w1 = wbits(W_hh, W_ih, c, row, col + 1);
                a[mt][ks][rg] = w0 | (w1 << 16);
            }
        }
    }

    __syncthreads();
    if (tid == 0) publish(&g_flags[cta * 32], base + 1);
    if (tid < 128) poll_flag_sleep(&g_flags[tid * 32], base + 1);
    __syncthreads();

    // epilogue mapping
    const int ebl = tid & 15, ehl = tid >> 4;
    float c_reg = 0.f;

    // staging assignment constants (thread handles a = tid, tid+256[, tid+512])
    const int sks0 = tid >> 4;            // 0..15
    const int sks1 = 16 + (tid >> 4);     // 16..31

    for (int t = 0; t < Tn; ++t) {
        // ---- poll the two h-source flags this thread stages ----
        {
            const unsigned tgt = base + (unsigned)t + 1;
            spin1(&g_flags[(g * 32 + sks0) * 32], tgt);
            spin1(&g_flags[(g * 32 + sks1) * 32], tgt);
            __syncwarp();
        }
        // ---- stage B tiles (fragment-linear, split hi/lo) ----
        {
            int na = (tid < 32) ? 3 : 2;
            #pragma unroll
            for (int ai = 0; ai < 3; ++ai) {
                if (ai >= na) break;
                int aa = tid + ai * 256;
                int ks = aa >> 4, b = aa & 15;
                const uint4* src;
                if (ks < 32)
                    src = (const uint4*)(g_hpk + ((size_t)t * NG + g) * 8192 +
                                         b * 512 + ks * 16);
                else
                    src = (const uint4*)(g_xpk + ((size_t)t * NG + g) * 512 +
                                         b * 32 + (ks - 32) * 16);
                uint4 q0 = __ldcg(src + 0), q1 = __ldcg(src + 1);
                uint4 q2 = __ldcg(src + 2), q3 = __ldcg(src + 3);
                unsigned w[16] = {q0.x, q0.y, q0.z, q0.w, q1.x, q1.y, q1.z, q1.w,
                                  q2.x, q2.y, q2.z, q2.w, q3.x, q3.y, q3.z, q3.w};
                int nt = b >> 3, g2 = b & 7;
                uint32_t bh = sb + OFF_BHI + (ks * 2 + nt) * 256 + g2 * 32;
                uint32_t blo = sb + OFF_BLO + (ks * 2 + nt) * 256 + g2 * 32;
                #pragma unroll
                for (int t4 = 0; t4 < 4; ++t4) {
                    unsigned h0 = __byte_perm(w[2 * t4],     w[2 * t4 + 1], 0x5410);
                    unsigned h1 = __byte_perm(w[2 * t4 + 8], w[2 * t4 + 9], 0x5410);
                    sts64(bh + t4 * 8, h0, h1);
                    unsigned l0 = __byte_perm(w[2 * t4],     w[2 * t4 + 1], 0x7632);
                    unsigned l1 = __byte_perm(w[2 * t4 + 8], w[2 * t4 + 9], 0x7632);
                    sts64(blo + t4 * 8, l0, l1);
                }
            }
        }
        __syncthreads();

        // ---- GEMM: 2 passes (B_hi, B_lo) x 17 ksteps, A from registers ----
        float acc[2][2][4];
        #pragma unroll
        for (int mt = 0; mt < 2; ++mt)
            #pragma unroll
            for (int nt = 0; nt < 2; ++nt)
                #pragma unroll
                for (int j = 0; j < 4; ++j) acc[mt][nt][j] = 0.f;

        #pragma unroll
        for (int pass = 0; pass < 2; ++pass) {
            uint32_t tb = sb + (pass ? OFF_BLO : OFF_BHI);
            #pragma unroll
            for (int ks = 0; ks < 17; ++ks) {
                int ksg = kh * 17 + ks;
                uint32_t addr = tb + ksg * 512 + lane * 8;
                uint32_t b00, b01, b10, b11;
                lds64(b00, b01, addr);
                lds64(b10, b11, addr + 256);
                MMA16816(acc[0][0], a[0][ks], b00, b01);
                MMA16816(acc[0][1], a[0][ks], b10, b11);
                MMA16816(acc[1][0], a[1][ks], b00, b01);
                MMA16816(acc[1][1], a[1][ks], b10, b11);
            }
        }

        // ---- store partials: sm_r[part][64 r][20] ----
        {
            int part = kh * 2 + (ms >> 1);
            float* rp = smf + OFF_R / 4 + part * 64 * 20;
            int rbase = 32 * (ms & 1) + fg;
            #pragma unroll
            for (int mt = 0; mt < 2; ++mt) {
                #pragma unroll
                for (int nt = 0; nt < 2; ++nt) {
                    int R = rbase + 16 * mt;
                    int col = 8 * nt + 2 * ft;
                    *(float2*)(rp + R * 20 + col) =
                        make_float2(acc[mt][nt][0], acc[mt][nt][1]);
                    *(float2*)(rp + (R + 8) * 20 + col) =
                        make_float2(acc[mt][nt][2], acc[mt][nt][3]);
                }
            }
        }
        __syncthreads();

        // ---- reduce 4 partials -> gates in sm_r[0] ----
        {
            int r = tid >> 2, b4 = tid & 3;
            float* rp0 = smf + OFF_R / 4;
            float4 s0 = *(float4*)(rp0 + (0 * 64 + r) * 20 + b4 * 4);
            float4 s1 = *(float4*)(rp0 + (1 * 64 + r) * 20 + b4 * 4);
            float4 s2 = *(float4*)(rp0 + (2 * 64 + r) * 20 + b4 * 4);
            float4 s3 = *(float4*)(rp0 + (3 * 64 + r) * 20 + b4 * 4);
            *(float4*)(rp0 + r * 20 + b4 * 4) =
                make_float4(s0.x + s1.x + s2.x + s3.x,
                            s0.y + s1.y + s2.y + s3.y,
                            s0.z + s1.z + s2.z + s3.z,
                            s0.w + s1.w + s2.w + s3.w);
        }
        __syncthreads();

        // ---- LSTM cell epilogue ----
        {
            const float* gb = smf + OFF_R / 4;
            float xi = gb[( 0 + ehl) * 20 + ebl] + sm_bias[ 0 + ehl];
            float xf = gb[(16 + ehl) * 20 + ebl] + sm_bias[16 + ehl];
            float xg = gb[(32 + ehl) * 20 + ebl] + sm_bias[32 + ehl];
            float xo = gb[(48 + ehl) * 20 + ebl] + sm_bias[48 + ehl];
            float ei = ex2f(-xi * L2E);
            float ef = ex2f(-xf * L2E);
            float eo = ex2f(-xo * L2E);
            float eg = ex2f(-2.f * xg * L2E);
            float di = 1.f + ei, df = 1.f + ef, dc = 1.f + eo, dg = 1.f + eg;
            float q0 = rcpf(di * df);
            float ii = q0 * df, ff = q0 * di;
            float q1 = rcpf(dc * dg);
            float oo = q1 * dg;
            float tg = (1.f - eg) * (q1 * dc);
            c_reg = ff * c_reg + ii * tg;
            float ec = ex2f(-2.f * c_reg * L2E);
            float tc = (1.f - ec) * rcpf(1.f + ec);
            float h  = oo * tc;
            g_hpk[(((size_t)(t + 1) * NG + g) * 16 + ebl) * 512 + c * 16 + ehl] =
                packhl(h);
        }
        __syncthreads();
        if (tid == 0) publish(&g_flags[cta * 32], base + (unsigned)t + 2);
    }

    // ================= conv tail =================
    if (tid < 32)
        poll_flag_sleep(&g_flags[(g * 32 + tid) * 32], base + Tn + 1);
    __syncthreads();

    float* scw  = smf + OFF_BHI / 4;      // reuse B tiles
    float* sred = scw + 512;
    for (int i = tid; i < Hn; i += NTHR) scw[i] = cw[i];
    const float cbv = cb[0];
    __syncthreads();

    const int cb2 = tid >> 4, cs = tid & 15;
    for (int j = 0; j < Tn / GC; ++j) {
        int t = c * (Tn / GC) + j;
        const unsigned* hp =
            g_hpk + (((size_t)(t + 1) * NG + g) * 16 + cb2) * 512 + cs * 32;
        float acc = 0.f;
        #pragma unroll 8
        for (int h = 0; h < 32; ++h) {
            unsigned w = __ldcg(hp + h);
            float hv = __uint_as_float(w << 16) +
                       __uint_as_float(w & 0xFFFF0000u);
            acc += hv * scw[cs * 32 + h];
        }
        sred[tid] = acc;
        __syncthreads();
        if (tid < 16) {
            float s = cbv;
            #pragma unroll
            for (int q = 0; q < 16; ++q) s += sred[tid * 16 + q];
            out[(size_t)(g * 16 + tid) * Tn + t] = s;
        }
        __syncthreads();
    }
}

// ---------------------------------------------------------------------------
extern "C" void kernel_launch(void* const* d_in, const int* in_sizes, int n_in,
                              void* d_out, int out_size)
{
    const float* x    = (const float*)d_in[0];
    const float* W_ih = (const float*)d_in[1];
    const float* W_hh = (const float*)d_in[2];
    const float* b_ih = (const float*)d_in[3];
    const float* b_hh = (const float*)d_in[4];
    const float* cw   = (const float*)d_in[5];
    const float* cb   = (const float*)d_in[6];
    float* out = (float*)d_out;

    cudaFuncSetAttribute(lstm_hmma_kernel,
                         cudaFuncAttributeMaxDynamicSharedMemorySize, SMEM_TOTAL);
    lstm_hmma_kernel<<<NCTA, NTHR, SMEM_TOTAL>>>(x, W_ih, W_hh, b_ih, b_hh,
                                                 cw, cb, out);
}